// round 1
// baseline (speedup 1.0000x reference)
#include <cuda_runtime.h>

// Problem constants (fixed by setup_inputs):
//   coefficients: [64, 256, 45] f32
//   NOShfS=16, NOShfR=16, NOShfA=8, NOShfZ=8
//   output row = 12*(16+16) + 66*8*8 = 384 + 4224 = 4608 f32
#define NBLK    16384        // 64*256 (n,a) pairs
#define NCOEFF  45
#define ROWLEN  4608

// Source index table for the 12 orbital vectors (36 floats):
//   p  = coeff[9:21]                        -> vectors 0..3
//   d  = coeff[21:45] reshape [4,6], last-dim permuted [0,2,5,4,3,1],
//        reshape [8,3]                      -> vectors 4..11
__constant__ int c_src[36] = {
     9, 10, 11, 12, 13, 14, 15, 16, 17, 18, 19, 20,   // p
    21, 23, 26, 25, 24, 22,                            // d group 0
    27, 29, 32, 31, 30, 28,                            // d group 1
    33, 35, 38, 37, 36, 34,                            // d group 2
    39, 41, 44, 43, 42, 40                             // d group 3
};

// triu_indices(12, k=1), i-major (66 pairs)
__constant__ unsigned char c_iu[66] = {
    0,0,0,0,0,0,0,0,0,0,0,
    1,1,1,1,1,1,1,1,1,1,
    2,2,2,2,2,2,2,2,2,
    3,3,3,3,3,3,3,3,
    4,4,4,4,4,4,4,
    5,5,5,5,5,5,
    6,6,6,6,6,
    7,7,7,7,
    8,8,8,
    9,9,
    10
};
__constant__ unsigned char c_ju[66] = {
    1,2,3,4,5,6,7,8,9,10,11,
    2,3,4,5,6,7,8,9,10,11,
    3,4,5,6,7,8,9,10,11,
    4,5,6,7,8,9,10,11,
    5,6,7,8,9,10,11,
    6,7,8,9,10,11,
    7,8,9,10,11,
    8,9,10,11,
    9,10,11,
    10,11,
    11
};

// cos/sin of shfZ[k] = (2k+1)*pi/16  (linspace(pi/16, 15pi/16, 8))
__constant__ float c_cz[8] = {
     0.98078528f,  0.83146961f,  0.55557023f,  0.19509032f,
    -0.19509032f, -0.55557023f, -0.83146961f, -0.98078528f
};
__constant__ float c_sz[8] = {
     0.19509032f,  0.55557023f,  0.83146961f,  0.98078528f,
     0.98078528f,  0.83146961f,  0.55557023f,  0.19509032f
};

__global__ void __launch_bounds__(128, 8)
aev_kernel(const float* __restrict__ coeff, float* __restrict__ out)
{
    const int blk = blockIdx.x;     // flat (n*256 + a)
    const int t   = threadIdx.x;

    __shared__ float s_nv[12][3];
    __shared__ float s_dist[12];
    __shared__ __align__(16) float s_rad[192];   // [12][16]  (s_aev == r_aev)
    __shared__ float s_f1[528];                  // [66][8]  includes the 2x factor
    __shared__ __align__(16) float s_f2[528];    // [66][8]

    // ---- Phase A: orbital vectors, norms, normalized vectors ----
    const float* cp = coeff + (size_t)blk * NCOEFF;
    if (t < 12) {
        float x = __ldg(cp + c_src[t * 3 + 0]);
        float y = __ldg(cp + c_src[t * 3 + 1]);
        float z = __ldg(cp + c_src[t * 3 + 2]);
        float d = sqrtf(fmaf(x, x, fmaf(y, y, z * z)));
        bool zero = (fabsf(x) < 1e-12f) & (fabsf(y) < 1e-12f) & (fabsf(z) < 1e-12f);
        float inv = zero ? 0.0f : 1.0f / d;
        s_nv[t][0] = x * inv;
        s_nv[t][1] = y * inv;
        s_nv[t][2] = z * inv;
        s_dist[t]  = d;
    }
    __syncthreads();

    // ---- Phase B: radial staging: rad[v][s] = exp(-16*(d_v - shf_s)^2), shf = 0.5 + 0.2*s
    #pragma unroll
    for (int i = t; i < 192; i += 128) {
        int v = i >> 4, s = i & 15;
        float diff = s_dist[v] - fmaf((float)s, 0.2f, 0.5f);
        s_rad[i] = __expf(-16.0f * diff * diff);
    }

    // ---- Phase C: per-pair angular factors ----
    if (t < 66) {
        int i = c_iu[t], j = c_ju[t];
        float dotv = s_nv[i][0] * s_nv[j][0]
                   + s_nv[i][1] * s_nv[j][1]
                   + s_nv[i][2] * s_nv[j][2];
        float c = 0.95f * dotv;                       // = cos(angle)
        float s = sqrtf(fmaxf(1.0f - c * c, 0.0f));   // = sin(angle), angle in [0,pi]
        float avd = 0.5f * (s_dist[i] + s_dist[j]);
        #pragma unroll
        for (int z = 0; z < 8; z++) {
            // cos(angle - shfZ[z]) = c*cz + s*sz   (no arccos needed)
            float base = 0.5f * (1.0f + fmaf(c, c_cz[z], s * c_sz[z]));
            float p = base * base;   // ^2
            p = p * p;               // ^4
            p = p * p;               // ^8
            p = p * p;               // ^16
            p = p * p;               // ^32
            s_f1[t * 8 + z] = 2.0f * p;
        }
        #pragma unroll
        for (int a = 0; a < 8; a++) {
            float diff = avd - fmaf((float)a, 0.42857143f, 0.5f);  // shfA = 0.5 + 3/7*a
            s_f2[t * 8 + a] = __expf(-8.0f * diff * diff);
        }
    }
    __syncthreads();

    // ---- Phase D: coalesced float4 streaming write of the 4608-float row ----
    float4* orow = reinterpret_cast<float4*>(out + (size_t)blk * ROWLEN);
    #pragma unroll
    for (int it = 0; it < 9; it++) {
        int e4   = it * 128 + t;   // float4 index, 0..1151
        int elem = e4 << 2;        // float index within row
        float4 val;
        if (elem < 384) {
            // radial: v = elem/32, shf index = elem%16 (s_aev duplicated as r_aev)
            int v = elem >> 5;
            int s = elem & 15;
            val = *reinterpret_cast<const float4*>(&s_rad[v * 16 + s]);
        } else {
            int ae  = elem - 384;          // 0..4223
            int pz  = ae >> 3;             // pair*8 + z
            int pa  = ((ae >> 6) << 3) + (ae & 7);  // pair*8 + a  (a in {0,4})
            float  f1 = s_f1[pz];
            float4 f2 = *reinterpret_cast<const float4*>(&s_f2[pa]);
            val = make_float4(f1 * f2.x, f1 * f2.y, f1 * f2.z, f1 * f2.w);
        }
        __stcs(&orow[e4], val);
    }
}

extern "C" void kernel_launch(void* const* d_in, const int* in_sizes, int n_in,
                              void* d_out, int out_size)
{
    const float* coeff = (const float*)d_in[0];
    float* out = (float*)d_out;
    aev_kernel<<<NBLK, 128>>>(coeff, out);
}